// round 12
// baseline (speedup 1.0000x reference)
#include <cuda_runtime.h>
#include <cuda_bf16.h>

#define EE 256
#define NH 8
#define HD 32
#define NB 16
#define NQ 100
#define NS 4096

typedef unsigned long long ull;

// ---- packed f32x2 helpers (sm_103a, PTX ISA 8.6+) ----
__device__ __forceinline__ ull pk2(float lo, float hi) {
    ull r; asm("mov.b64 %0,{%1,%2};" : "=l"(r) : "f"(lo), "f"(hi)); return r;
}
__device__ __forceinline__ void upk2(ull v, float& lo, float& hi) {
    asm("mov.b64 {%0,%1},%2;" : "=f"(lo), "=f"(hi) : "l"(v));
}
__device__ __forceinline__ ull fma2(ull a, ull b, ull c) {
    ull d; asm("fma.rn.f32x2 %0,%1,%2,%3;" : "=l"(d) : "l"(a), "l"(b), "l"(c)); return d;
}
__device__ __forceinline__ ull add2(ull a, ull b) {
    ull d; asm("add.rn.f32x2 %0,%1,%2;" : "=l"(d) : "l"(a), "l"(b)); return d;
}
__device__ __forceinline__ ull mul2(ull a, ull b) {
    ull d; asm("mul.rn.f32x2 %0,%1,%2;" : "=l"(d) : "l"(a), "l"(b)); return d;
}
__device__ __forceinline__ float ex2f(float x) {
    float y; asm("ex2.approx.f32 %0,%1;" : "=f"(y) : "f"(x)); return y;
}
// 16B async copy global->shared (Ampere+ LDGSTS)
__device__ __forceinline__ void cp16(unsigned dst, const void* src) {
    asm volatile("cp.async.cg.shared.global [%0], [%1], 16;"
                 :: "r"(dst), "l"(__cvta_generic_to_global(src)) : "memory");
}

// Scratch (allocation-free rule: __device__ globals)
__device__ float gK[NB * NH * NS * HD];      // (B,H,S,D)
__device__ float gV[NB * NH * NS * HD];      // (B,H,S,D)
__device__ float gQp[NB * NQ * EE];          // (B*Q, E)
__device__ float gAO[NB * NQ * EE];          // (B*Q, E)
__device__ unsigned int gM[NB * NQ * (NS / 32)]; // bit-packed mask, 128 words/row
__device__ int gMaskIsBytes;                 // 1 = uint8 bools, 0 = int32 0/1

// ---------------------------------------------------------------------------
// Mask layout detection. For int32-encoded 0/1 values every byte at
// idx%4 != 0 is zero; for byte-bools ~half of them are 1. Checking 768
// such bytes makes misdetection probability ~2^-768. Deterministic.
// ---------------------------------------------------------------------------
__global__ void mask_detect(const unsigned char* __restrict__ mask)
{
    const int tid = threadIdx.x;   // 256 threads, bytes [0,1024)
    int v = mask[tid * 4 + 1] | mask[tid * 4 + 2] | mask[tid * 4 + 3];
    int any = __syncthreads_or(v);
    if (tid == 0) gMaskIsBytes = any ? 1 : 0;
}

// ---------------------------------------------------------------------------
// Mask bit-pack: one thread per output word (32 mask elements -> 32 bits).
// ---------------------------------------------------------------------------
__device__ __forceinline__ unsigned int lsb8(ull v) {
    return (unsigned int)(((v & 0x0101010101010101ULL) * 0x0102040810204080ULL) >> 56);
}

__global__ __launch_bounds__(256) void mask_pack(const unsigned char* __restrict__ mask)
{
    int idx = blockIdx.x * 256 + threadIdx.x;   // word index, < NB*NQ*128
    unsigned int w;
    if (gMaskIsBytes) {
        const ull* src = (const ull*)(mask + (size_t)idx * 32);
        w = lsb8(src[0]) | (lsb8(src[1]) << 8) | (lsb8(src[2]) << 16) | (lsb8(src[3]) << 24);
    } else {
        const uint4* src = (const uint4*)(mask + (size_t)idx * 128);
        w = 0u;
        #pragma unroll
        for (int i = 0; i < 8; i++) {
            uint4 v = src[i];
            w |= (unsigned int)(v.x != 0u) << (4 * i);
            w |= (unsigned int)(v.y != 0u) << (4 * i + 1);
            w |= (unsigned int)(v.z != 0u) << (4 * i + 2);
            w |= (unsigned int)(v.w != 0u) << (4 * i + 3);
        }
    }
    gM[idx] = w;
}

// ---------------------------------------------------------------------------
// Fused K/V projection GEMM, double-buffered + software-pipelined.
//   kin[b,s,e] = image_features[b,e,s] + pos_image[b,s,e]
//   vin[b,s,e] = image_features[b,e,s]
//   K[b,h,s,d] = sum_e kin * Wk[n,e] + bk[n],  n = h*32+d   (same for V)
// Tile: 64 (s) x 64 (n), BK=16, 256 threads, 4x4 per thread, both K and V.
// Weights pre-packed (w,w) in smem (inner loop: 16 FFMA2 + 12 LDS.64).
// Epilogue: stage 64x64 tile (bias added) in smem, write coalesced float4
// lines (removes ~4x store-sector inflation of the scattered layout).
// ---------------------------------------------------------------------------
#define KVBUF_ULL 3136   // per-buffer size in ull units (25088 B)
#define EPI_STRIDE 68    // floats per staged row (272B, 16B-aligned rows)

__global__ __launch_bounds__(256) void kv_gemm(
    const float* __restrict__ img,   // (B,E,S)
    const float* __restrict__ posi,  // (B,S,E)
    const float* __restrict__ Wk, const float* __restrict__ bk,
    const float* __restrict__ Wv, const float* __restrict__ bv)
{
    const int n0 = blockIdx.x * 64;
    const int s0 = blockIdx.y * 64;
    const int b  = blockIdx.z;

    extern __shared__ ull dsm[];     // 2 x KVBUF_ULL

    const int tid = threadIdx.x;
    const int tx = tid & 15;         // n-quad
    const int ty = tid >> 4;         // m-quad
    const int lkk  = tid & 15;       // loader: k within step (pos/weights)
    const int lmm0 = tid >> 4;       // loader: base m/n (pos/weights)

    ull acck2[2][4] = {};            // [m-pair][n], packed (m, m+1)
    ull accv2[2][4] = {};

    const float* imgB = img  + (size_t)b * EE * NS;
    const float* posB = posi + (size_t)b * NS * EE;

    float rimg[4], rpos[4], rwk[4], rwv[4];

    // prologue: stage iter 0
    {
        const int k0 = 0;
        #pragma unroll
        for (int i = 0; i < 4; i++) {
            int lin = i * 256 + tid;
            int mm = lin & 63, kk = lin >> 6;
            rimg[i] = imgB[(k0 + kk) * NS + s0 + mm];
        }
        #pragma unroll
        for (int i = 0; i < 4; i++) {
            int mm = lmm0 + i * 16;
            rpos[i] = posB[(s0 + mm) * EE + k0 + lkk];
            rwk[i]  = Wk[(n0 + mm) * EE + k0 + lkk];
            rwv[i]  = Wv[(n0 + mm) * EE + k0 + lkk];
        }
    }

    int p = 0;
    for (int kt = 0; kt < 16; kt++) {
        // buffer-p pointers: [Bk2 | Bv2 | Ak | Av]
        ull*   Bk2 = dsm + p * KVBUF_ULL;
        ull*   Bv2 = Bk2 + 1040;            // 16*65
        float* Akf = (float*)(Bv2 + 1040);  // 16*66 floats
        float* Avf = Akf + 1056;

        // stores from staged registers
        #pragma unroll
        for (int i = 0; i < 4; i++) {
            int lin = i * 256 + tid;
            int mm = lin & 63, kk = lin >> 6;
            Avf[kk * 66 + mm] = rimg[i];
        }
        #pragma unroll
        for (int i = 0; i < 4; i++) {
            int mm = lmm0 + i * 16;
            Akf[lkk * 66 + mm] = rpos[i];
            Bk2[lkk * 65 + mm] = pk2(rwk[i], rwk[i]);
            Bv2[lkk * 65 + mm] = pk2(rwv[i], rwv[i]);
        }
        __syncthreads();

        // add pass: Ak = pos + img
        #pragma unroll
        for (int i = 0; i < 4; i++) {
            int lin = i * 256 + tid;
            int mm = lin & 63, kk = lin >> 6;
            Akf[kk * 66 + mm] += Avf[kk * 66 + mm];
        }

        // stage iter kt+1 (overlaps with compute below)
        if (kt < 15) {
            const int k0 = (kt + 1) * 16;
            #pragma unroll
            for (int i = 0; i < 4; i++) {
                int lin = i * 256 + tid;
                int mm = lin & 63, kk = lin >> 6;
                rimg[i] = imgB[(k0 + kk) * NS + s0 + mm];
            }
            #pragma unroll
            for (int i = 0; i < 4; i++) {
                int mm = lmm0 + i * 16;
                rpos[i] = posB[(s0 + mm) * EE + k0 + lkk];
                rwk[i]  = Wk[(n0 + mm) * EE + k0 + lkk];
                rwv[i]  = Wv[(n0 + mm) * EE + k0 + lkk];
            }
        }
        __syncthreads();

        // compute from buffer p
        #pragma unroll
        for (int kk = 0; kk < 16; kk++) {
            ull ak2_0 = *(const ull*)&Akf[kk * 66 + ty * 4];
            ull ak2_1 = *(const ull*)&Akf[kk * 66 + ty * 4 + 2];
            ull av2_0 = *(const ull*)&Avf[kk * 66 + ty * 4];
            ull av2_1 = *(const ull*)&Avf[kk * 66 + ty * 4 + 2];
            #pragma unroll
            for (int j = 0; j < 4; j++) {
                ull wk2 = Bk2[kk * 65 + tx * 4 + j];
                ull wv2 = Bv2[kk * 65 + tx * 4 + j];
                acck2[0][j] = fma2(ak2_0, wk2, acck2[0][j]);
                acck2[1][j] = fma2(ak2_1, wk2, acck2[1][j]);
                accv2[0][j] = fma2(av2_0, wv2, accv2[0][j]);
                accv2[1][j] = fma2(av2_1, wv2, accv2[1][j]);
            }
        }
        p ^= 1;
    }

    // Epilogue: stage (bias added) in smem [s][n], then coalesced writes.
    // Buffer reuse is safe only after all threads exit the compute loop.
    __syncthreads();
    float* Kst = (float*)dsm;                 // [64][EPI_STRIDE] = 17408 B
    float* Vst = Kst + 64 * EPI_STRIDE;       // + 17408 B = 34816 <= 50176
    #pragma unroll
    for (int i2 = 0; i2 < 2; i2++) {
        #pragma unroll
        for (int j = 0; j < 4; j++) {
            float k_lo, k_hi, v_lo, v_hi;
            upk2(acck2[i2][j], k_lo, k_hi);
            upk2(accv2[i2][j], v_lo, v_hi);
            int nn = tx * 4 + j;              // 0..63
            float bkv = bk[n0 + nn], bvv = bv[n0 + nn];
            int sr = ty * 4 + 2 * i2;         // 0..62 even
            Kst[sr * EPI_STRIDE + nn]       = k_lo + bkv;
            Kst[(sr + 1) * EPI_STRIDE + nn] = k_hi + bkv;
            Vst[sr * EPI_STRIDE + nn]       = v_lo + bvv;
            Vst[(sr + 1) * EPI_STRIDE + nn] = v_hi + bvv;
        }
    }
    __syncthreads();
    #pragma unroll
    for (int it = 0; it < 4; it++) {
        int lin = it * 256 + tid;             // 0..1023 float4 slots
        int sr = lin >> 4;                    // 64 rows
        int n4 = (lin & 15) * 4;              // n offset 0..60 (mult of 4)
        int gn = n0 + n4;
        int hh = gn >> 5, dd = gn & 31;       // dd multiple of 4, dd+3 <= 31
        size_t o = ((size_t)(b * NH + hh) * NS + s0 + sr) * HD + dd;
        *(float4*)&gK[o] = *(const float4*)&Kst[sr * EPI_STRIDE + n4];
        *(float4*)&gV[o] = *(const float4*)&Vst[sr * EPI_STRIDE + n4];
    }
}

// ---------------------------------------------------------------------------
// Generic C[m,n] = (A1[m,k] + A2[m,k]) @ W[n,k]^T + bias[n]  (f32x2 inner,
// packed weights), double-buffered + register-staged (one barrier/iter:
// compute(kt-1) reads buf ~p, barrier B(kt) follows it, and the next writes
// of ~p occur in iter kt+1, after B(kt) on every thread — no race).
// A row-major (M,256), W (256,256). Tile 64x64, BK=16.
// ---------------------------------------------------------------------------
__global__ __launch_bounds__(256) void gemm_abT(
    const float* __restrict__ A1, const float* __restrict__ A2,
    const float* __restrict__ W, const float* __restrict__ bias,
    float* __restrict__ C)
{
    const int n0 = blockIdx.x * 64;
    const int m0 = blockIdx.y * 64;

    __shared__ float As[2][16][66];
    __shared__ ull   Bs2[2][16][65];

    const int tid = threadIdx.x;
    const int tx = tid & 15;
    const int ty = tid >> 4;
    const int lkk  = tid & 15;
    const int lmm0 = tid >> 4;

    ull acc2[2][4] = {};

    float ra[4], rw[4];

    // prologue: stage iter 0
    #pragma unroll
    for (int i = 0; i < 4; i++) {
        int mm = lmm0 + i * 16;
        float a = A1[(m0 + mm) * EE + lkk];
        if (A2) a += A2[(m0 + mm) * EE + lkk];
        ra[i] = a;
        rw[i] = W[(n0 + mm) * EE + lkk];
    }

    int p = 0;
    for (int kt = 0; kt < 16; kt++) {
        // stores from staged registers into buffer p
        #pragma unroll
        for (int i = 0; i < 4; i++) {
            int mm = lmm0 + i * 16;
            As[p][lkk][mm]  = ra[i];
            Bs2[p][lkk][mm] = pk2(rw[i], rw[i]);
        }
        __syncthreads();

        // stage iter kt+1 (overlaps with compute below)
        if (kt < 15) {
            const int k0 = (kt + 1) * 16;
            #pragma unroll
            for (int i = 0; i < 4; i++) {
                int mm = lmm0 + i * 16;
                float a = A1[(m0 + mm) * EE + k0 + lkk];
                if (A2) a += A2[(m0 + mm) * EE + k0 + lkk];
                ra[i] = a;
                rw[i] = W[(n0 + mm) * EE + k0 + lkk];
            }
        }

        // compute from buffer p
        #pragma unroll
        for (int kk = 0; kk < 16; kk++) {
            ull a2_0 = *(const ull*)&As[p][kk][ty * 4];
            ull a2_1 = *(const ull*)&As[p][kk][ty * 4 + 2];
            #pragma unroll
            for (int j = 0; j < 4; j++) {
                ull w2 = Bs2[p][kk][tx * 4 + j];
                acc2[0][j] = fma2(a2_0, w2, acc2[0][j]);
                acc2[1][j] = fma2(a2_1, w2, acc2[1][j]);
            }
        }
        p ^= 1;
    }

    #pragma unroll
    for (int i2 = 0; i2 < 2; i2++) {
        #pragma unroll
        for (int j = 0; j < 4; j++) {
            float lo, hi;
            upk2(acc2[i2][j], lo, hi);
            int n = n0 + tx * 4 + j;
            int m = m0 + ty * 4 + 2 * i2;
            C[m * EE + n]        = lo + bias[n];
            C[(m + 1) * EE + n]  = hi + bias[n];
        }
    }
}

// ---------------------------------------------------------------------------
// Flash-style attention, cp.async double-buffered, 512 threads = 4 s-groups
// of 128 (4 warps/SMSP for latency cover); thread q = tid&127 owns query q.
// Max-free softmax (scores are O(10): exp cannot overflow fp32) so split-S
// partial states merge by pure addition (4-way). K/V tiles (256 keys, 64KB)
// stream through 2 x 64KB smem buffers via cp.async, overlapping the next
// tile's loads with the current tile's compute. Mask words register-staged
// one tile ahead. log2(e) folded into the q scale; exp = single ex2.approx.
// ---------------------------------------------------------------------------
__global__ __launch_bounds__(512) void attn_flash()
{
    const int h = blockIdx.x;
    const int b = blockIdx.y;

    const int tid = threadIdx.x;
    const int grp = tid >> 7;       // s-split group 0..3
    const int lq  = tid & 127;      // query index
    const bool valid = lq < NQ;
    const int qidx = valid ? lq : 0;

    extern __shared__ float4 sm4[]; // 2 buffers x 4096 float4 (K 2048 | V 2048)
    const unsigned smbase = (unsigned)__cvta_generic_to_shared(sm4);

    // 1/sqrt(32) * log2(e): fold softmax scale and exp->ex2 conversion
    const float kscale = 0.17677669529663687f * 1.4426950408889634f;
    const ull scl2 = pk2(kscale, kscale);

    // Query vector in registers, packed pairs, pre-scaled
    ull qv2[16];
    {
        const float4* qrow = (const float4*)(gQp + ((size_t)b * NQ + qidx) * EE + h * HD);
        #pragma unroll
        for (int j = 0; j < 8; j++) {
            float4 t = qrow[j];
            qv2[2 * j]     = mul2(pk2(t.x, t.y), scl2);
            qv2[2 * j + 1] = mul2(pk2(t.z, t.w), scl2);
        }
    }

    const float4* Kb4 = (const float4*)(gK + (size_t)(b * NH + h) * NS * HD);
    const float4* Vb4 = (const float4*)(gV + (size_t)(b * NH + h) * NS * HD);
    const unsigned int* mrow = gM + (size_t)(b * NQ + qidx) * (NS / 32);

    float l = 0.f;
    ull acc2[16];
    #pragma unroll
    for (int j = 0; j < 16; j++) acc2[j] = 0ull;

    // prologue: async-issue tile 0 into buffer 0 (512 threads x 4 iters x 2);
    // stage tile-0 mask words (2 per group of 64 keys)
    #pragma unroll
    for (int i = 0; i < 4; i++) {
        int f = i * 512 + tid;
        cp16(smbase + (unsigned)(f) * 16u,          Kb4 + f);
        cp16(smbase + (unsigned)(2048 + f) * 16u,   Vb4 + f);
    }
    asm volatile("cp.async.commit_group;" ::: "memory");
    unsigned st0 = mrow[grp * 2];
    unsigned st1 = mrow[grp * 2 + 1];

    for (int t = 0; t < 16; t++) {
        const int cur = t & 1;
        if (t < 15) {
            // issue tile t+1 into the other buffer (free since iter t-1's
            // trailing barrier), then wait for tile t (<=1 group pending)
            const int base = (cur ^ 1) * 4096;
            const int goff = (t + 1) * 2048;
            #pragma unroll
            for (int i = 0; i < 4; i++) {
                int f = i * 512 + tid;
                cp16(smbase + (unsigned)(base + f) * 16u,        Kb4 + goff + f);
                cp16(smbase + (unsigned)(base + 2048 + f) * 16u, Vb4 + goff + f);
            }
            asm volatile("cp.async.commit_group;" ::: "memory");
            asm volatile("cp.async.wait_group 1;" ::: "memory");
        } else {
            asm volatile("cp.async.wait_group 0;" ::: "memory");
        }
        __syncthreads();

        // mask words for this tile (from staging regs); stage t+1 during compute
        const unsigned mw0 = st0, mw1 = st1;
        if (t < 15) {
            const int wb = (t + 1) * 8 + grp * 2;
            st0 = mrow[wb];
            st1 = mrow[wb + 1];
        }

        const float4* Ks4 = sm4 + cur * 4096;
        const float4* Vs4 = Ks4 + 2048;
        const int sbase = grp * 64;     // this group's 64 keys within the tile
        #pragma unroll
        for (int g = 0; g < 2; g++) {
            const unsigned mw = (g == 0) ? mw0 : mw1;
            #pragma unroll 2
            for (int i = 0; i < 32; i++) {
                const int s = sbase + g * 32 + i;
                const ulonglong2* krow = (const ulonglong2*)(Ks4 + s * 8);
                // 4 independent packed dot-product chains
                ull sA = 0ull, sB = 0ull, sC = 0ull, sD = 0ull;
                #pragma unroll
                for (int j = 0; j < 4; j++) {
                    ulonglong2 k0 = krow[2 * j];
                    ulonglong2 k1 = krow[2 * j + 1];
                    sA = fma2(k0.x, qv2[4 * j],     sA);
                    sB = fma2(k0.y, qv2[4 * j + 1], sB);
                    sC = fma2(k1.x, qv2[4 * j + 2], sC);
                    sD = fma2(k1.y, qv2[4 * j + 3], sD);
                }
                ull sE = add2(add2(sA, sB), add2(sC, sD));
                float s_lo, s_hi; upk2(sE, s_lo, s_hi);
                float sc = s_lo + s_hi;    // already includes log2(e) factor

                float p = ((mw >> i) & 1u) ? ex2f(sc) : 0.f;
                l += p;
                ull p2 = pk2(p, p);

                const ulonglong2* vrow = (const ulonglong2*)(Vs4 + s * 8);
                #pragma unroll
                for (int j = 0; j < 8; j++) {
                    ulonglong2 vv = vrow[j];
                    acc2[2 * j]     = fma2(p2, vv.x, acc2[2 * j]);
                    acc2[2 * j + 1] = fma2(p2, vv.y, acc2[2 * j + 1]);
                }
            }
        }
        __syncthreads();   // buffer cur free for reuse at iter t+1's issue
    }

    // Additive 4-way merge (no max => states add directly).
    // Groups 1..3 spill (16 ull + l) rows; group 0 reduces. 3*128 rows x
    // 18 ull = 55296 B, fits the 128KB smem area (tiles are done).
    ull* mbuf = (ull*)sm4;          // rows of 18 u64 = 144B (16B-aligned)
    if (grp > 0) {
        ull* row = mbuf + ((grp - 1) * 128 + lq) * 18;
        #pragma unroll
        for (int j = 0; j < 16; j++) row[j] = acc2[j];
        ((float*)(row + 16))[0] = l;
    }
    __syncthreads();
    if (grp == 0 && valid) {
        #pragma unroll
        for (int gg = 0; gg < 3; gg++) {
            ull* row = mbuf + (gg * 128 + lq) * 18;
            #pragma unroll
            for (int j = 0; j < 16; j++) acc2[j] = add2(acc2[j], row[j]);
            l += ((float*)(row + 16))[0];
        }
        const float inv = 1.0f / l;
        const ull inv2 = pk2(inv, inv);
        ulonglong2* orow = (ulonglong2*)(gAO + ((size_t)b * NQ + lq) * EE + h * HD);
        #pragma unroll
        for (int j = 0; j < 8; j++) {
            ulonglong2 o;
            o.x = mul2(acc2[2 * j], inv2);
            o.y = mul2(acc2[2 * j + 1], inv2);
            orow[j] = o;
        }
    }
}

// ---------------------------------------------------------------------------
extern "C" void kernel_launch(void* const* d_in, const int* in_sizes, int n_in,
                              void* d_out, int out_size)
{
    const float* qf   = (const float*)d_in[0];   // (B,Q,E)
    const float* imf  = (const float*)d_in[1];   // (B,E,H,W)
    const unsigned char* mask = (const unsigned char*)d_in[2]; // (B,Q,H,W) bool/int32
    const float* pq   = (const float*)d_in[3];   // (B,Q,E)
    const float* pi   = (const float*)d_in[4];   // (B,S,E)
    const float* Wq   = (const float*)d_in[5];
    const float* bq   = (const float*)d_in[6];
    const float* Wk   = (const float*)d_in[7];
    const float* bk   = (const float*)d_in[8];
    const float* Wv   = (const float*)d_in[9];
    const float* bv   = (const float*)d_in[10];
    const float* Wo   = (const float*)d_in[11];
    const float* bo   = (const float*)d_in[12];
    float* out = (float*)d_out;

    float *pQp, *pAO;
    cudaGetSymbolAddress((void**)&pQp, gQp);
    cudaGetSymbolAddress((void**)&pAO, gAO);

    // Unconditional (no static guards allowed); idempotent, capture-legal.
    cudaFuncSetAttribute(attn_flash,
                         cudaFuncAttributeMaxDynamicSharedMemorySize, 131072);
    cudaFuncSetAttribute(kv_gemm,
                         cudaFuncAttributeMaxDynamicSharedMemorySize, 2 * KVBUF_ULL * 8);

    // 0) Detect mask encoding (uint8 vs int32), then bit-pack it.
    mask_detect<<<1, 256>>>(mask);
    mask_pack<<<800, 256>>>(mask);
    // 1) K/V projections (fused, double-buffered)
    kv_gemm<<<dim3(4, 64, NB), 256, 2 * KVBUF_ULL * 8>>>(imf, pi, Wk, bk, Wv, bv);
    // 2) Q projection: (B*Q=1600, 256) — 1600 = 25*64
    gemm_abT<<<dim3(4, 25), 256>>>(qf, pq, Wq, bq, pQp);
    // 3) Attention: one block per (b,h), 512 threads, 128KB dynamic smem
    attn_flash<<<dim3(NH, NB), 512, 131072>>>();
    // 4) Output projection
    gemm_abT<<<dim3(4, 25), 256>>>(pAO, nullptr, Wo, bo, out);
}

// round 13
// speedup vs baseline: 1.6433x; 1.6433x over previous
#include <cuda_runtime.h>
#include <cuda_bf16.h>

#define EE 256
#define NH 8
#define HD 32
#define NB 16
#define NQ 100
#define NS 4096

typedef unsigned long long ull;

// ---- packed f32x2 helpers (sm_103a, PTX ISA 8.6+) ----
__device__ __forceinline__ ull pk2(float lo, float hi) {
    ull r; asm("mov.b64 %0,{%1,%2};" : "=l"(r) : "f"(lo), "f"(hi)); return r;
}
__device__ __forceinline__ void upk2(ull v, float& lo, float& hi) {
    asm("mov.b64 {%0,%1},%2;" : "=f"(lo), "=f"(hi) : "l"(v));
}
__device__ __forceinline__ ull fma2(ull a, ull b, ull c) {
    ull d; asm("fma.rn.f32x2 %0,%1,%2,%3;" : "=l"(d) : "l"(a), "l"(b), "l"(c)); return d;
}
__device__ __forceinline__ ull add2(ull a, ull b) {
    ull d; asm("add.rn.f32x2 %0,%1,%2;" : "=l"(d) : "l"(a), "l"(b)); return d;
}
__device__ __forceinline__ ull mul2(ull a, ull b) {
    ull d; asm("mul.rn.f32x2 %0,%1,%2;" : "=l"(d) : "l"(a), "l"(b)); return d;
}
__device__ __forceinline__ float ex2f(float x) {
    float y; asm("ex2.approx.f32 %0,%1;" : "=f"(y) : "f"(x)); return y;
}
// 16B async copy global->shared (Ampere+ LDGSTS)
__device__ __forceinline__ void cp16(unsigned dst, const void* src) {
    asm volatile("cp.async.cg.shared.global [%0], [%1], 16;"
                 :: "r"(dst), "l"(__cvta_generic_to_global(src)) : "memory");
}

// Scratch (allocation-free rule: __device__ globals)
__device__ float gK[NB * NH * NS * HD];      // (B,H,S,D)
__device__ float gV[NB * NH * NS * HD];      // (B,H,S,D)
__device__ float gQp[NB * NQ * EE];          // (B*Q, E)
__device__ float gAO[NB * NQ * EE];          // (B*Q, E)
__device__ unsigned int gM[NB * NQ * (NS / 32)]; // bit-packed mask, 128 words/row
__device__ int gMaskIsBytes;                 // 1 = uint8 bools, 0 = int32 0/1

// ---------------------------------------------------------------------------
// Mask layout detection (uint8 bools vs int32 0/1). Deterministic.
// ---------------------------------------------------------------------------
__global__ void mask_detect(const unsigned char* __restrict__ mask)
{
    const int tid = threadIdx.x;   // 256 threads, bytes [0,1024)
    int v = mask[tid * 4 + 1] | mask[tid * 4 + 2] | mask[tid * 4 + 3];
    int any = __syncthreads_or(v);
    if (tid == 0) gMaskIsBytes = any ? 1 : 0;
}

// ---------------------------------------------------------------------------
// Mask bit-pack: one thread per output word (32 mask elements -> 32 bits).
// blockBase shifts the word range so the pack can be split into 3 launches
// (pure launch-index engineering: puts kv_gemm at ncu's -s 5 profile slot).
// ---------------------------------------------------------------------------
__device__ __forceinline__ unsigned int lsb8(ull v) {
    return (unsigned int)(((v & 0x0101010101010101ULL) * 0x0102040810204080ULL) >> 56);
}

__global__ __launch_bounds__(256) void mask_pack(const unsigned char* __restrict__ mask,
                                                 int blockBase)
{
    int idx = (blockBase + blockIdx.x) * 256 + threadIdx.x;   // word index
    if (idx >= NB * NQ * (NS / 32)) return;
    unsigned int w;
    if (gMaskIsBytes) {
        const ull* src = (const ull*)(mask + (size_t)idx * 32);
        w = lsb8(src[0]) | (lsb8(src[1]) << 8) | (lsb8(src[2]) << 16) | (lsb8(src[3]) << 24);
    } else {
        const uint4* src = (const uint4*)(mask + (size_t)idx * 128);
        w = 0u;
        #pragma unroll
        for (int i = 0; i < 8; i++) {
            uint4 v = src[i];
            w |= (unsigned int)(v.x != 0u) << (4 * i);
            w |= (unsigned int)(v.y != 0u) << (4 * i + 1);
            w |= (unsigned int)(v.z != 0u) << (4 * i + 2);
            w |= (unsigned int)(v.w != 0u) << (4 * i + 3);
        }
    }
    gM[idx] = w;
}

// ---------------------------------------------------------------------------
// Fused K/V projection GEMM, double-buffered + software-pipelined.
// Weight smem layout is [kk][j*16 + tx] (element n=tx*4+j stored at j*16+tx):
// compute-phase lanes tx=0..15 read 8B-apart -> banks 0,2,..,30 CONFLICT-FREE
// (the previous [kk][n] layout was 4-way conflicted on every weight LDS.64 —
// measured as L1=44.9% vs fma=8.2% on the sibling gemm kernel).
// Epilogue: stage tile in smem, write coalesced float4 lines.
// ---------------------------------------------------------------------------
#define KVBUF_ULL 3136   // per-buffer size in ull units (25088 B)
#define EPI_STRIDE 68    // floats per staged row (272B, 16B-aligned rows)

__global__ __launch_bounds__(256) void kv_gemm(
    const float* __restrict__ img,   // (B,E,S)
    const float* __restrict__ posi,  // (B,S,E)
    const float* __restrict__ Wk, const float* __restrict__ bk,
    const float* __restrict__ Wv, const float* __restrict__ bv)
{
    const int n0 = blockIdx.x * 64;
    const int s0 = blockIdx.y * 64;
    const int b  = blockIdx.z;

    extern __shared__ ull dsm[];     // 2 x KVBUF_ULL

    const int tid = threadIdx.x;
    const int tx = tid & 15;         // n-quad
    const int ty = tid >> 4;         // m-quad
    const int lkk  = tid & 15;       // loader: k within step (pos/weights)
    const int lmm0 = tid >> 4;       // loader: base m/n (pos/weights)

    ull acck2[2][4] = {};            // [m-pair][n], packed (m, m+1)
    ull accv2[2][4] = {};

    const float* imgB = img  + (size_t)b * EE * NS;
    const float* posB = posi + (size_t)b * NS * EE;

    float rimg[4], rpos[4], rwk[4], rwv[4];

    // prologue: stage iter 0
    {
        const int k0 = 0;
        #pragma unroll
        for (int i = 0; i < 4; i++) {
            int lin = i * 256 + tid;
            int mm = lin & 63, kk = lin >> 6;
            rimg[i] = imgB[(k0 + kk) * NS + s0 + mm];
        }
        #pragma unroll
        for (int i = 0; i < 4; i++) {
            int mm = lmm0 + i * 16;
            rpos[i] = posB[(s0 + mm) * EE + k0 + lkk];
            rwk[i]  = Wk[(n0 + mm) * EE + k0 + lkk];
            rwv[i]  = Wv[(n0 + mm) * EE + k0 + lkk];
        }
    }

    int p = 0;
    for (int kt = 0; kt < 16; kt++) {
        // buffer-p pointers: [Bk2 | Bv2 | Ak | Av]
        ull*   Bk2 = dsm + p * KVBUF_ULL;
        ull*   Bv2 = Bk2 + 1040;            // 16*65
        float* Akf = (float*)(Bv2 + 1040);  // 16*66 floats
        float* Avf = Akf + 1056;

        // stores from staged registers
        #pragma unroll
        for (int i = 0; i < 4; i++) {
            int lin = i * 256 + tid;
            int mm = lin & 63, kk = lin >> 6;
            Avf[kk * 66 + mm] = rimg[i];
        }
        #pragma unroll
        for (int i = 0; i < 4; i++) {
            int mm = lmm0 + i * 16;
            Akf[lkk * 66 + mm] = rpos[i];
            int widx = lkk * 65 + ((mm & 3) << 4) + (mm >> 2);   // [kk][j*16+tx]
            Bk2[widx] = pk2(rwk[i], rwk[i]);
            Bv2[widx] = pk2(rwv[i], rwv[i]);
        }
        __syncthreads();

        // add pass: Ak = pos + img
        #pragma unroll
        for (int i = 0; i < 4; i++) {
            int lin = i * 256 + tid;
            int mm = lin & 63, kk = lin >> 6;
            Akf[kk * 66 + mm] += Avf[kk * 66 + mm];
        }

        // stage iter kt+1 (overlaps with compute below)
        if (kt < 15) {
            const int k0 = (kt + 1) * 16;
            #pragma unroll
            for (int i = 0; i < 4; i++) {
                int lin = i * 256 + tid;
                int mm = lin & 63, kk = lin >> 6;
                rimg[i] = imgB[(k0 + kk) * NS + s0 + mm];
            }
            #pragma unroll
            for (int i = 0; i < 4; i++) {
                int mm = lmm0 + i * 16;
                rpos[i] = posB[(s0 + mm) * EE + k0 + lkk];
                rwk[i]  = Wk[(n0 + mm) * EE + k0 + lkk];
                rwv[i]  = Wv[(n0 + mm) * EE + k0 + lkk];
            }
        }
        __syncthreads();

        // compute from buffer p
        #pragma unroll
        for (int kk = 0; kk < 16; kk++) {
            ull ak2_0 = *(const ull*)&Akf[kk * 66 + ty * 4];
            ull ak2_1 = *(const ull*)&Akf[kk * 66 + ty * 4 + 2];
            ull av2_0 = *(const ull*)&Avf[kk * 66 + ty * 4];
            ull av2_1 = *(const ull*)&Avf[kk * 66 + ty * 4 + 2];
            #pragma unroll
            for (int j = 0; j < 4; j++) {
                ull wk2 = Bk2[kk * 65 + (j << 4) + tx];   // conflict-free
                ull wv2 = Bv2[kk * 65 + (j << 4) + tx];
                acck2[0][j] = fma2(ak2_0, wk2, acck2[0][j]);
                acck2[1][j] = fma2(ak2_1, wk2, acck2[1][j]);
                accv2[0][j] = fma2(av2_0, wv2, accv2[0][j]);
                accv2[1][j] = fma2(av2_1, wv2, accv2[1][j]);
            }
        }
        p ^= 1;
    }

    // Epilogue: stage (bias added) in smem [s][n], then coalesced writes.
    __syncthreads();
    float* Kst = (float*)dsm;                 // [64][EPI_STRIDE] = 17408 B
    float* Vst = Kst + 64 * EPI_STRIDE;       // + 17408 B = 34816 <= 50176
    #pragma unroll
    for (int i2 = 0; i2 < 2; i2++) {
        #pragma unroll
        for (int j = 0; j < 4; j++) {
            float k_lo, k_hi, v_lo, v_hi;
            upk2(acck2[i2][j], k_lo, k_hi);
            upk2(accv2[i2][j], v_lo, v_hi);
            int nn = tx * 4 + j;              // 0..63
            float bkv = bk[n0 + nn], bvv = bv[n0 + nn];
            int sr = ty * 4 + 2 * i2;         // 0..62 even
            Kst[sr * EPI_STRIDE + nn]       = k_lo + bkv;
            Kst[(sr + 1) * EPI_STRIDE + nn] = k_hi + bkv;
            Vst[sr * EPI_STRIDE + nn]       = v_lo + bvv;
            Vst[(sr + 1) * EPI_STRIDE + nn] = v_hi + bvv;
        }
    }
    __syncthreads();
    #pragma unroll
    for (int it = 0; it < 4; it++) {
        int lin = it * 256 + tid;             // 0..1023 float4 slots
        int sr = lin >> 4;                    // 64 rows
        int n4 = (lin & 15) * 4;              // n offset 0..60 (mult of 4)
        int gn = n0 + n4;
        int hh = gn >> 5, dd = gn & 31;       // dd multiple of 4, dd+3 <= 31
        size_t o = ((size_t)(b * NH + hh) * NS + s0 + sr) * HD + dd;
        *(float4*)&gK[o] = *(const float4*)&Kst[sr * EPI_STRIDE + n4];
        *(float4*)&gV[o] = *(const float4*)&Vst[sr * EPI_STRIDE + n4];
    }
}

// ---------------------------------------------------------------------------
// Generic C[m,n] = (A1[m,k] + A2[m,k]) @ W[n,k]^T + bias[n]  (f32x2 inner,
// packed weights in the conflict-free [kk][j*16+tx] layout), double-buffered
// + register-staged, one barrier/iter. Tile 64x64, BK=16.
// ---------------------------------------------------------------------------
__global__ __launch_bounds__(256) void gemm_abT(
    const float* __restrict__ A1, const float* __restrict__ A2,
    const float* __restrict__ W, const float* __restrict__ bias,
    float* __restrict__ C)
{
    const int n0 = blockIdx.x * 64;
    const int m0 = blockIdx.y * 64;

    __shared__ float As[2][16][66];
    __shared__ ull   Bs2[2][16][65];

    const int tid = threadIdx.x;
    const int tx = tid & 15;
    const int ty = tid >> 4;
    const int lkk  = tid & 15;
    const int lmm0 = tid >> 4;

    ull acc2[2][4] = {};

    float ra[4], rw[4];

    // prologue: stage iter 0
    #pragma unroll
    for (int i = 0; i < 4; i++) {
        int mm = lmm0 + i * 16;
        float a = A1[(m0 + mm) * EE + lkk];
        if (A2) a += A2[(m0 + mm) * EE + lkk];
        ra[i] = a;
        rw[i] = W[(n0 + mm) * EE + lkk];
    }

    int p = 0;
    for (int kt = 0; kt < 16; kt++) {
        // stores from staged registers into buffer p
        #pragma unroll
        for (int i = 0; i < 4; i++) {
            int mm = lmm0 + i * 16;
            As[p][lkk][mm] = ra[i];
            Bs2[p][lkk][((mm & 3) << 4) + (mm >> 2)] = pk2(rw[i], rw[i]);
        }
        __syncthreads();

        // stage iter kt+1 (overlaps with compute below)
        if (kt < 15) {
            const int k0 = (kt + 1) * 16;
            #pragma unroll
            for (int i = 0; i < 4; i++) {
                int mm = lmm0 + i * 16;
                float a = A1[(m0 + mm) * EE + k0 + lkk];
                if (A2) a += A2[(m0 + mm) * EE + k0 + lkk];
                ra[i] = a;
                rw[i] = W[(n0 + mm) * EE + k0 + lkk];
            }
        }

        // compute from buffer p
        #pragma unroll
        for (int kk = 0; kk < 16; kk++) {
            ull a2_0 = *(const ull*)&As[p][kk][ty * 4];
            ull a2_1 = *(const ull*)&As[p][kk][ty * 4 + 2];
            #pragma unroll
            for (int j = 0; j < 4; j++) {
                ull w2 = Bs2[p][kk][(j << 4) + tx];   // conflict-free
                acc2[0][j] = fma2(a2_0, w2, acc2[0][j]);
                acc2[1][j] = fma2(a2_1, w2, acc2[1][j]);
            }
        }
        p ^= 1;
    }

    #pragma unroll
    for (int i2 = 0; i2 < 2; i2++) {
        #pragma unroll
        for (int j = 0; j < 4; j++) {
            float lo, hi;
            upk2(acc2[i2][j], lo, hi);
            int n = n0 + tx * 4 + j;
            int m = m0 + ty * 4 + 2 * i2;
            C[m * EE + n]        = lo + bias[n];
            C[(m + 1) * EE + n]  = hi + bias[n];
        }
    }
}

// ---------------------------------------------------------------------------
// Flash-style attention, cp.async double-buffered, 512 threads = 4 s-groups
// of 128; thread q = tid&127 owns query q. Max-free softmax (scores O(10))
// so split-S states merge additively (4-way). Smem reads are warp-broadcast
// (all lanes same key row) — conflict-free by construction.
// ---------------------------------------------------------------------------
__global__ __launch_bounds__(512) void attn_flash()
{
    const int h = blockIdx.x;
    const int b = blockIdx.y;

    const int tid = threadIdx.x;
    const int grp = tid >> 7;       // s-split group 0..3
    const int lq  = tid & 127;      // query index
    const bool valid = lq < NQ;
    const int qidx = valid ? lq : 0;

    extern __shared__ float4 sm4[]; // 2 buffers x 4096 float4 (K 2048 | V 2048)
    const unsigned smbase = (unsigned)__cvta_generic_to_shared(sm4);

    // 1/sqrt(32) * log2(e): fold softmax scale and exp->ex2 conversion
    const float kscale = 0.17677669529663687f * 1.4426950408889634f;
    const ull scl2 = pk2(kscale, kscale);

    // Query vector in registers, packed pairs, pre-scaled
    ull qv2[16];
    {
        const float4* qrow = (const float4*)(gQp + ((size_t)b * NQ + qidx) * EE + h * HD);
        #pragma unroll
        for (int j = 0; j < 8; j++) {
            float4 t = qrow[j];
            qv2[2 * j]     = mul2(pk2(t.x, t.y), scl2);
            qv2[2 * j + 1] = mul2(pk2(t.z, t.w), scl2);
        }
    }

    const float4* Kb4 = (const float4*)(gK + (size_t)(b * NH + h) * NS * HD);
    const float4* Vb4 = (const float4*)(gV + (size_t)(b * NH + h) * NS * HD);
    const unsigned int* mrow = gM + (size_t)(b * NQ + qidx) * (NS / 32);

    float l = 0.f;
    ull acc2[16];
    #pragma unroll
    for (int j = 0; j < 16; j++) acc2[j] = 0ull;

    // prologue: async-issue tile 0 into buffer 0; stage tile-0 mask words
    #pragma unroll
    for (int i = 0; i < 4; i++) {
        int f = i * 512 + tid;
        cp16(smbase + (unsigned)(f) * 16u,          Kb4 + f);
        cp16(smbase + (unsigned)(2048 + f) * 16u,   Vb4 + f);
    }
    asm volatile("cp.async.commit_group;" ::: "memory");
    unsigned st0 = mrow[grp * 2];
    unsigned st1 = mrow[grp * 2 + 1];

    for (int t = 0; t < 16; t++) {
        const int cur = t & 1;
        if (t < 15) {
            const int base = (cur ^ 1) * 4096;
            const int goff = (t + 1) * 2048;
            #pragma unroll
            for (int i = 0; i < 4; i++) {
                int f = i * 512 + tid;
                cp16(smbase + (unsigned)(base + f) * 16u,        Kb4 + goff + f);
                cp16(smbase + (unsigned)(base + 2048 + f) * 16u, Vb4 + goff + f);
            }
            asm volatile("cp.async.commit_group;" ::: "memory");
            asm volatile("cp.async.wait_group 1;" ::: "memory");
        } else {
            asm volatile("cp.async.wait_group 0;" ::: "memory");
        }
        __syncthreads();

        const unsigned mw0 = st0, mw1 = st1;
        if (t < 15) {
            const int wb = (t + 1) * 8 + grp * 2;
            st0 = mrow[wb];
            st1 = mrow[wb + 1];
        }

        const float4* Ks4 = sm4 + cur * 4096;
        const float4* Vs4 = Ks4 + 2048;
        const int sbase = grp * 64;     // this group's 64 keys within the tile
        #pragma unroll
        for (int g = 0; g < 2; g++) {
            const unsigned mw = (g == 0) ? mw0 : mw1;
            #pragma unroll 2
            for (int i = 0; i < 32; i++) {
                const int s = sbase + g * 32 + i;
                const ulonglong2* krow = (const ulonglong2*)(Ks4 + s * 8);
                ull sA = 0ull, sB = 0ull, sC = 0ull, sD = 0ull;
                #pragma unroll
                for (int j = 0; j < 4; j++) {
                    ulonglong2 k0 = krow[2 * j];
                    ulonglong2 k1 = krow[2 * j + 1];
                    sA = fma2(k0.x, qv2[4 * j],     sA);
                    sB = fma2(k0.y, qv2[4 * j + 1], sB);
                    sC = fma2(k1.x, qv2[4 * j + 2], sC);
                    sD = fma2(k1.y, qv2[4 * j + 3], sD);
                }
                ull sE = add2(add2(sA, sB), add2(sC, sD));
                float s_lo, s_hi; upk2(sE, s_lo, s_hi);
                float sc = s_lo + s_hi;    // already includes log2(e) factor

                float p = ((mw >> i) & 1u) ? ex2f(sc) : 0.f;
                l += p;
                ull p2 = pk2(p, p);

                const ulonglong2* vrow = (const ulonglong2*)(Vs4 + s * 8);
                #pragma unroll
                for (int j = 0; j < 8; j++) {
                    ulonglong2 vv = vrow[j];
                    acc2[2 * j]     = fma2(p2, vv.x, acc2[2 * j]);
                    acc2[2 * j + 1] = fma2(p2, vv.y, acc2[2 * j + 1]);
                }
            }
        }
        __syncthreads();   // buffer cur free for reuse at iter t+1's issue
    }

    // Additive 4-way merge. Groups 1..3 spill; group 0 reduces.
    ull* mbuf = (ull*)sm4;          // rows of 18 u64 = 144B (16B-aligned)
    if (grp > 0) {
        ull* row = mbuf + ((grp - 1) * 128 + lq) * 18;
        #pragma unroll
        for (int j = 0; j < 16; j++) row[j] = acc2[j];
        ((float*)(row + 16))[0] = l;
    }
    __syncthreads();
    if (grp == 0 && valid) {
        #pragma unroll
        for (int gg = 0; gg < 3; gg++) {
            ull* row = mbuf + (gg * 128 + lq) * 18;
            #pragma unroll
            for (int j = 0; j < 16; j++) acc2[j] = add2(acc2[j], row[j]);
            l += ((float*)(row + 16))[0];
        }
        const float inv = 1.0f / l;
        const ull inv2 = pk2(inv, inv);
        ulonglong2* orow = (ulonglong2*)(gAO + ((size_t)b * NQ + lq) * EE + h * HD);
        #pragma unroll
        for (int j = 0; j < 8; j++) {
            ulonglong2 o;
            o.x = mul2(acc2[2 * j], inv2);
            o.y = mul2(acc2[2 * j + 1], inv2);
            orow[j] = o;
        }
    }
}

// ---------------------------------------------------------------------------
extern "C" void kernel_launch(void* const* d_in, const int* in_sizes, int n_in,
                              void* d_out, int out_size)
{
    const float* qf   = (const float*)d_in[0];   // (B,Q,E)
    const float* imf  = (const float*)d_in[1];   // (B,E,H,W)
    const unsigned char* mask = (const unsigned char*)d_in[2]; // (B,Q,H,W) bool/int32
    const float* pq   = (const float*)d_in[3];   // (B,Q,E)
    const float* pi   = (const float*)d_in[4];   // (B,S,E)
    const float* Wq   = (const float*)d_in[5];
    const float* bq   = (const float*)d_in[6];
    const float* Wk   = (const float*)d_in[7];
    const float* bk   = (const float*)d_in[8];
    const float* Wv   = (const float*)d_in[9];
    const float* bv   = (const float*)d_in[10];
    const float* Wo   = (const float*)d_in[11];
    const float* bo   = (const float*)d_in[12];
    float* out = (float*)d_out;

    float *pQp, *pAO;
    cudaGetSymbolAddress((void**)&pQp, gQp);
    cudaGetSymbolAddress((void**)&pAO, gAO);

    // Unconditional (no static guards allowed); idempotent, capture-legal.
    cudaFuncSetAttribute(attn_flash,
                         cudaFuncAttributeMaxDynamicSharedMemorySize, 131072);
    cudaFuncSetAttribute(kv_gemm,
                         cudaFuncAttributeMaxDynamicSharedMemorySize, 2 * KVBUF_ULL * 8);

    // Launch order puts kv_gemm at index 5 = ncu's profiled launch (-s 5 -c 1).
    // 0) detect; 1-3) mask pack in 3 slices; 4) Q proj; 5) kv_gemm; 6) attn; 7) O proj
    mask_detect<<<1, 256>>>(mask);
    mask_pack<<<267, 256>>>(mask, 0);
    mask_pack<<<267, 256>>>(mask, 267);
    mask_pack<<<266, 256>>>(mask, 534);
    gemm_abT<<<dim3(4, 25), 256>>>(qf, pq, Wq, bq, pQp);
    kv_gemm<<<dim3(4, 64, NB), 256, 2 * KVBUF_ULL * 8>>>(imf, pi, Wk, bk, Wv, bv);
    attn_flash<<<dim3(NH, NB), 512, 131072>>>();
    gemm_abT<<<dim3(4, 25), 256>>>(pAO, nullptr, Wo, bo, out);
}